// round 1
// baseline (speedup 1.0000x reference)
#include <cuda_runtime.h>
#include <float.h>

// Problem constants
#define B_  4
#define C_  64
#define T_  32
#define WH_ 4096                 // W*H
#define PLANE_ (T_ * WH_)        // per-channel plane: 131072 floats
#define PLANE4_ (PLANE_ / 4)     // 32768 float4
#define FRAME4_ (WH_ / 4)        // 1024 float4 per (b,t) frame

__device__ __forceinline__ float sigmoidf_(float v) {
    return 1.0f / (1.0f + __expf(-v));
}

// Kernel 1: fused channel mean/max pooling + sigmoid + skin add + per-frame softmax.
// One block per (b,t) frame. 512 threads, each owns 2 float4 = 8 spatial positions.
__global__ __launch_bounds__(512) void fusion_softmax_kernel(
    const float* __restrict__ x,
    const float* __restrict__ skin,
    float* __restrict__ attn)
{
    const int bt  = blockIdx.x;          // 0..B_*T_-1 (128)
    const int b   = bt >> 5;             // / T_
    const int t   = bt & 31;             // % T_
    const int tid = threadIdx.x;         // 0..511

    // float4 base index of this frame within channel 0
    const size_t f4base = ((size_t)b * C_ * T_ + t) * FRAME4_;
    const float4* __restrict__ x4 = (const float4*)x;

    float4 s0 = make_float4(0.f, 0.f, 0.f, 0.f);
    float4 s1 = make_float4(0.f, 0.f, 0.f, 0.f);
    float4 m0 = make_float4(-FLT_MAX, -FLT_MAX, -FLT_MAX, -FLT_MAX);
    float4 m1 = m0;

    #pragma unroll 4
    for (int c = 0; c < C_; c++) {
        const size_t base = f4base + (size_t)c * PLANE4_;
        const float4 v0 = x4[base + tid];
        const float4 v1 = x4[base + tid + 512];
        s0.x += v0.x; s0.y += v0.y; s0.z += v0.z; s0.w += v0.w;
        s1.x += v1.x; s1.y += v1.y; s1.z += v1.z; s1.w += v1.w;
        m0.x = fmaxf(m0.x, v0.x); m0.y = fmaxf(m0.y, v0.y);
        m0.z = fmaxf(m0.z, v0.z); m0.w = fmaxf(m0.w, v0.w);
        m1.x = fmaxf(m1.x, v1.x); m1.y = fmaxf(m1.y, v1.y);
        m1.z = fmaxf(m1.z, v1.z); m1.w = fmaxf(m1.w, v1.w);
    }

    // skin for this frame
    const float4* __restrict__ sk4 = (const float4*)skin;
    const size_t skbase = (size_t)bt * FRAME4_;
    const float4 k0 = sk4[skbase + tid];
    const float4 k1 = sk4[skbase + tid + 512];

    const float inv_c = 1.0f / (float)C_;
    float f[8];
    f[0] = sigmoidf_(s0.x * inv_c) + sigmoidf_(m0.x) + k0.x;
    f[1] = sigmoidf_(s0.y * inv_c) + sigmoidf_(m0.y) + k0.y;
    f[2] = sigmoidf_(s0.z * inv_c) + sigmoidf_(m0.z) + k0.z;
    f[3] = sigmoidf_(s0.w * inv_c) + sigmoidf_(m0.w) + k0.w;
    f[4] = sigmoidf_(s1.x * inv_c) + sigmoidf_(m1.x) + k1.x;
    f[5] = sigmoidf_(s1.y * inv_c) + sigmoidf_(m1.y) + k1.y;
    f[6] = sigmoidf_(s1.z * inv_c) + sigmoidf_(m1.z) + k1.z;
    f[7] = sigmoidf_(s1.w * inv_c) + sigmoidf_(m1.w) + k1.w;

    __shared__ float red[16];

    // ---- block max over 4096 values ----
    float lm = f[0];
    #pragma unroll
    for (int i = 1; i < 8; i++) lm = fmaxf(lm, f[i]);
    #pragma unroll
    for (int o = 16; o; o >>= 1) lm = fmaxf(lm, __shfl_xor_sync(0xffffffffu, lm, o));
    if ((tid & 31) == 0) red[tid >> 5] = lm;
    __syncthreads();
    if (tid < 32) {
        float v = (tid < 16) ? red[tid] : -FLT_MAX;
        #pragma unroll
        for (int o = 8; o; o >>= 1) v = fmaxf(v, __shfl_xor_sync(0xffffffffu, v, o));
        if (tid == 0) red[0] = v;
    }
    __syncthreads();
    const float M = red[0];
    __syncthreads();

    // ---- exp and block sum ----
    float e[8];
    float ls = 0.f;
    #pragma unroll
    for (int i = 0; i < 8; i++) { e[i] = __expf(f[i] - M); ls += e[i]; }
    #pragma unroll
    for (int o = 16; o; o >>= 1) ls += __shfl_xor_sync(0xffffffffu, ls, o);
    if ((tid & 31) == 0) red[tid >> 5] = ls;
    __syncthreads();
    if (tid < 32) {
        float v = (tid < 16) ? red[tid] : 0.f;
        #pragma unroll
        for (int o = 8; o; o >>= 1) v += __shfl_xor_sync(0xffffffffu, v, o);
        if (tid == 0) red[0] = v;
    }
    __syncthreads();
    const float inv_sum = __frcp_rn(red[0]);

    // ---- write attn (float4) ----
    float4* __restrict__ a4 = (float4*)attn;
    float4 o0, o1;
    o0.x = e[0] * inv_sum; o0.y = e[1] * inv_sum;
    o0.z = e[2] * inv_sum; o0.w = e[3] * inv_sum;
    o1.x = e[4] * inv_sum; o1.y = e[5] * inv_sum;
    o1.z = e[6] * inv_sum; o1.w = e[7] * inv_sum;
    a4[skbase + tid]       = o0;
    a4[skbase + tid + 512] = o1;
}

// Kernel 2: out[b,c,t,w,h] = x[b,c,t,w,h] * attn[b,t,w,h]
// blockIdx.y = b*C + c (256 planes), blockIdx.x covers the 32768 float4 of a plane.
__global__ __launch_bounds__(256) void apply_attn_kernel(
    const float* __restrict__ x,
    const float* __restrict__ attn,
    float* __restrict__ out)
{
    const int plane = blockIdx.y;            // 0..255
    const int b     = plane >> 6;            // / C_
    const int i4    = blockIdx.x * 256 + threadIdx.x;   // 0..32767

    const size_t px = (size_t)plane * PLANE4_ + i4;
    const size_t pa = (size_t)b * PLANE4_ + i4;          // attn: B*T*WH/4 per b == PLANE4_

    const float4 xv = ((const float4*)x)[px];
    const float4 av = ((const float4*)attn)[pa];
    float4 ov;
    ov.x = xv.x * av.x; ov.y = xv.y * av.y;
    ov.z = xv.z * av.z; ov.w = xv.w * av.w;
    ((float4*)out)[px] = ov;
}

extern "C" void kernel_launch(void* const* d_in, const int* in_sizes, int n_in,
                              void* d_out, int out_size)
{
    const float* x    = (const float*)d_in[0];
    const float* skin = (const float*)d_in[1];
    float* out  = (float*)d_out;
    float* attn = out + (size_t)B_ * C_ * T_ * WH_;   // second output region

    fusion_softmax_kernel<<<B_ * T_, 512>>>(x, skin, attn);

    dim3 grid(PLANE4_ / 256, B_ * C_);
    apply_attn_kernel<<<grid, 256>>>(x, attn, out);
}